// round 7
// baseline (speedup 1.0000x reference)
#include <cuda_runtime.h>
#include <cstdint>

#define T_STEPS 2048
#define B_SZ    16
#define D_SZ    1024
#define BD      (B_SZ*D_SZ)          /* 16384 */
#define NCTA    128
#define NTHR    256
#define HROWP   1088                 /* h_s b-row pitch: 16 chunks * (64+4) */
#define RPITCH  12                   /* reduce row pitch (8 + 4) */

// 128 MB scratch for the precomputed input projection (allowed: __device__ global)
__device__ float    g_xp[(size_t)T_STEPS * BD];
// dataflow flags: g_flag[t*128 + bg*64 + ng] != 0  <=>  h[t] rows bg*8..+8,
// cols ng*16..+16 are visible in global memory. Monotonic, 1MB, no reuse.
__device__ unsigned g_flag[(size_t)(T_STEPS + 1) * NCTA];

// ---------------- packed fp32x2 helpers (sm_100+ PTX) ----------------
__device__ __forceinline__ void ffma2(unsigned long long &d,
                                      unsigned long long a,
                                      unsigned long long b) {
    asm("fma.rn.f32x2 %0, %1, %2, %0;" : "+l"(d) : "l"(a), "l"(b));
}
__device__ __forceinline__ unsigned long long dup2(float a) {
    unsigned long long r;
    asm("mov.b64 %0, {%1, %1};" : "=l"(r) : "f"(a));
    return r;
}
__device__ __forceinline__ float2 unpack2(unsigned long long v) {
    float2 r;
    asm("mov.b64 {%0, %1}, %2;" : "=f"(r.x), "=f"(r.y) : "l"(v));
    return r;
}
__device__ __forceinline__ void cp16(uint32_t dst_smem, const void* src) {
    asm volatile("cp.async.cg.shared.global [%0], [%1], 16;"
                 :: "r"(dst_smem), "l"(src) : "memory");
}
#define CP_COMMIT() asm volatile("cp.async.commit_group;" ::: "memory")
#define CP_WAIT0()  asm volatile("cp.async.wait_group 0;" ::: "memory")

// ---------------- dataflow sync primitives ----------------
__device__ __forceinline__ void wait_flag(const unsigned* p) {
    unsigned v;
    do {
        asm volatile("ld.acquire.gpu.global.u32 %0, [%1];"
                     : "=r"(v) : "l"(p) : "memory");
    } while (v == 0u);
}
__device__ __forceinline__ void st_rel(unsigned* p, unsigned v) {
    asm volatile("st.release.gpu.global.u32 [%0], %1;"
                 :: "l"(p), "r"(v) : "memory");
}
__device__ __forceinline__ void fence_proxy_async_all() {
    asm volatile("fence.proxy.async;" ::: "memory");
}

// zero the flag array (runs once per kernel_launch; part of the graph)
__global__ void init_kernel() {
    const size_t N = (size_t)(T_STEPS + 1) * NCTA;
    for (size_t i = (size_t)blockIdx.x * blockDim.x + threadIdx.x; i < N;
         i += (size_t)gridDim.x * blockDim.x)
        g_flag[i] = 0u;
}

// ---------------------------------------------------------------------
// Kernel 1: xp[m,e] = sum_d x[m,d]*Wx[e,d] + b[e]   (unchanged)
// ---------------------------------------------------------------------
__global__ __launch_bounds__(256) void xp_gemm_kernel(
    const float* __restrict__ X,
    const float* __restrict__ Wx,
    const float* __restrict__ bias)
{
    __shared__ __align__(16) float As[16][68];
    __shared__ __align__(16) float Bs[16][68];

    const int tid   = threadIdx.x;
    const int mBase = blockIdx.y * 64;
    const int nBase = blockIdx.x * 64;

    const int lrow = tid >> 2;
    const int lk4  = (tid & 3) << 2;
    const int ty = tid >> 4;
    const int tx = tid & 15;

    unsigned long long acc[4][2];
#pragma unroll
    for (int i = 0; i < 4; i++) { acc[i][0] = 0ull; acc[i][1] = 0ull; }

    for (int k0 = 0; k0 < 1024; k0 += 16) {
        float4 av = *reinterpret_cast<const float4*>(
            &X[(size_t)(mBase + lrow) * 1024 + k0 + lk4]);
        float4 bv = *reinterpret_cast<const float4*>(
            &Wx[(size_t)(nBase + lrow) * 1024 + k0 + lk4]);
        As[lk4 + 0][lrow] = av.x; As[lk4 + 1][lrow] = av.y;
        As[lk4 + 2][lrow] = av.z; As[lk4 + 3][lrow] = av.w;
        Bs[lk4 + 0][lrow] = bv.x; Bs[lk4 + 1][lrow] = bv.y;
        Bs[lk4 + 2][lrow] = bv.z; Bs[lk4 + 3][lrow] = bv.w;
        __syncthreads();

#pragma unroll
        for (int k = 0; k < 16; k++) {
            float4 a = *reinterpret_cast<const float4*>(&As[k][ty << 2]);
            ulonglong2 bp = *reinterpret_cast<const ulonglong2*>(&Bs[k][tx << 2]);
            unsigned long long a0 = dup2(a.x), a1 = dup2(a.y);
            unsigned long long a2 = dup2(a.z), a3 = dup2(a.w);
            ffma2(acc[0][0], a0, bp.x); ffma2(acc[0][1], a0, bp.y);
            ffma2(acc[1][0], a1, bp.x); ffma2(acc[1][1], a1, bp.y);
            ffma2(acc[2][0], a2, bp.x); ffma2(acc[2][1], a2, bp.y);
            ffma2(acc[3][0], a3, bp.x); ffma2(acc[3][1], a3, bp.y);
        }
        __syncthreads();
    }

    const int col = nBase + (tx << 2);
    const float4 bv = *reinterpret_cast<const float4*>(&bias[col]);
#pragma unroll
    for (int m = 0; m < 4; m++) {
        const int row = mBase + (ty << 2) + m;
        float2 c01 = unpack2(acc[m][0]);
        float2 c23 = unpack2(acc[m][1]);
        float4 r;
        r.x = c01.x + bv.x; r.y = c01.y + bv.y;
        r.z = c23.x + bv.z; r.w = c23.y + bv.w;
        *reinterpret_cast<float4*>(&g_xp[(size_t)row * 1024 + col]) = r;
    }
}

// ---------------------------------------------------------------------
// Kernel 2: persistent recurrence, pure dataflow (NO global barrier).
// 128 CTAs x 256 threads. CTA = (bg = cta&1 -> 8 b-rows, ng = cta>>1 ->
// 16 columns). Per step each CTA stages only ITS 8 b-rows of h[t]
// (32KB; 4MB/step chip). Readiness is per-producer: thread tid stages
// the 16-col slice of producer p = tid>>2 after polling g_flag[t][bg][p]
// (ld.acquire spin). Producers release their flag right after their h
// stores. Fast CTAs run ahead; skew is absorbed, never globally re-paid.
// W_h register-resident; chunk-padded SMEM (64+4) keeps LDS.128
// conflict-free with 16-way lane broadcast.
// ---------------------------------------------------------------------
__global__ __launch_bounds__(256, 1) void recur_kernel(
    const float* __restrict__ Z,
    const float* __restrict__ H0,
    const float* __restrict__ Wh,
    const float* __restrict__ Gz,
    const float* __restrict__ Gh,
    const float* __restrict__ Bg,
    float* __restrict__ Out,
    float* __restrict__ Hout)
{
    extern __shared__ __align__(16) float sm[];
    float* h_s = sm;                      // 8 * HROWP floats (~34KB)
    float* red = sm + 8 * HROWP;          // 128 * RPITCH floats

    const int tid  = threadIdx.x;
    const int warp = tid >> 5;
    const int lane = tid & 31;
    const int cta  = blockIdx.x;

    const int bg    = cta & 1;            // batch group: rows bg*8..bg*8+7
    const int ng    = cta >> 1;           // column group: cols ng*16..+15
    const int bbase = bg * 8;

    const int n     = lane & 15;          // column within CTA (0..15)
    const int khalf = lane >> 4;          // 0/1
    const int ks    = warp * 2 + khalf;   // k-chunk 0..15 (64 k each)
    const int kbase = ks * 64;
    const int gcol  = ng * 16 + n;

    // ---- W_h slice (64 floats) -> registers, resident for all steps ----
    unsigned long long wx[16], wy[16];
    {
        const float* wp = Wh + (size_t)gcol * 1024 + kbase;
#pragma unroll
        for (int i = 0; i < 16; i++) {
            ulonglong2 v = *reinterpret_cast<const ulonglong2*>(wp + i * 4);
            wx[i] = v.x; wy[i] = v.y;
        }
    }

    // ---- staging role: thread owns producer slice p_sl = tid>>2 ----
    // slice = 16 cols x 8 b-rows (512B); this thread covers rows
    // {2*sub, 2*sub+1}, 4 x 16B pieces each.
    const int p_sl = tid >> 2;
    const int sub  = tid & 3;
    int dstw[8], srcw[8];
#pragma unroll
    for (int j = 0; j < 8; j++) {
        const int r  = 2 * sub + (j >> 2);
        const int pc = j & 3;
        dstw[j] = r * HROWP + (p_sl >> 2) * 68 + (p_sl & 3) * 16 + pc * 4;
        srcw[j] = r * 1024 + p_sl * 16 + pc * 4;
    }
    const uint32_t h_sh = (uint32_t)__cvta_generic_to_shared(h_s);
    const unsigned* cons_flag = g_flag + bg * 64 + p_sl;   // +128 per step
    unsigned* prod_flag = g_flag + NCTA + bg * 64 + ng;    // flag[t+1], +128/step

    // ---- epilogue role (threads 0..127): one output (b,n) each ----
    const int eb  = tid >> 4;             // local b 0..7
    const int en  = tid & 15;             // local n 0..15
    const int egb = bbase + eb;           // global b
    const int egc = ng * 16 + en;         // global col
    float gz_r = 0.f, gh_r = 0.f, bg_r = 0.f;
    if (tid < 128) {
        gz_r = Gz[egc]; gh_r = Gh[egc]; bg_r = Bg[egc];
        // h[0] = h0 (required output row 0; also the t=0 staging source)
        __stcg(&Hout[(size_t)egb * 1024 + egc], H0[(size_t)egb * 1024 + egc]);
    }
    __syncthreads();
    if (tid == 0) st_rel(&g_flag[bg * 64 + ng], 1u);   // h[0] slice ready

    for (int t = 0; t < T_STEPS; ++t) {
        // ---- prefetch epilogue operands (independent of h) ----
        float xpv = 0.f, zv = 0.f;
        size_t eidx = 0;
        if (tid < 128) {
            eidx = (size_t)t * BD + (size_t)egb * 1024 + egc;
            xpv = __ldcg(&g_xp[eidx]);
            zv  = __ldcg(&Z[eidx]);
        }

        // ---- dataflow staging: wait my producer, then cp my slice ----
        wait_flag(cons_flag + (size_t)t * NCTA);
        fence_proxy_async_all();
        const float* hrow = Hout + (size_t)t * BD + (size_t)bbase * 1024;
#pragma unroll
        for (int j = 0; j < 8; j++)
            cp16(h_sh + (uint32_t)dstw[j] * 4u, hrow + srcw[j]);
        CP_COMMIT();
        CP_WAIT0();
        __syncthreads();   // all slices visible in smem

        // ---- dot products: 512 MACs/thread over 8 b-rows ----
        unsigned long long accA[8], accB[8];
#pragma unroll
        for (int b = 0; b < 8; b++) { accA[b] = 0ull; accB[b] = 0ull; }
        const float* hc = h_s + ks * 68;
#pragma unroll
        for (int i = 0; i < 16; i++) {
#pragma unroll
            for (int b = 0; b < 8; b++) {
                ulonglong2 hv = *reinterpret_cast<const ulonglong2*>(
                    hc + b * HROWP + i * 4);
                ffma2(accA[b], hv.x, wx[i]);
                ffma2(accB[b], hv.y, wy[i]);
            }
        }

        // ---- reduce: khalf pair via shfl, then 8 warps via SMEM ----
        float s8[8];
#pragma unroll
        for (int b = 0; b < 8; b++) {
            float2 a = unpack2(accA[b]);
            float2 c = unpack2(accB[b]);
            s8[b] = (a.x + a.y) + (c.x + c.y);
            s8[b] += __shfl_xor_sync(0xffffffffu, s8[b], 16);
        }
        if (lane < 16) {
            float* rp = red + (warp * 16 + n) * RPITCH;
            *reinterpret_cast<float4*>(rp + 0) = make_float4(s8[0], s8[1], s8[2], s8[3]);
            *reinterpret_cast<float4*>(rp + 4) = make_float4(s8[4], s8[5], s8[6], s8[7]);
        }
        __syncthreads();

        // ---- final reduce (8 warp-partials) + h store ----
        float hn = 0.f, pre = 0.f;
        if (tid < 128) {
            float dot = 0.f;
#pragma unroll
            for (int w = 0; w < 8; w++)
                dot += red[(w * 16 + en) * RPITCH + eb];
            hn  = tanhf(xpv + dot);
            __stcg(&Hout[(size_t)(t + 1) * BD + (size_t)egb * 1024 + egc], hn);
            pre = zv * gz_r + hn * gh_r + bg_r;
        }
        __syncthreads();   // Hout stores issued (+ red/h_s safe) before release

        // ---- publish h[t+1] slice (consumers may proceed immediately) ----
        if (tid == 0) st_rel(prod_flag + (size_t)t * NCTA, 1u);

        // ---- gate + Out store: off the critical path ----
        if (tid < 128) {
            const float sg = 1.0f / (1.0f + __expf(-pre));
            __stcg(&Out[eidx], hn * (pre * sg));
        }
    }
}

// ---------------------------------------------------------------------
extern "C" void kernel_launch(void* const* d_in, const int* in_sizes, int n_in,
                              void* d_out, int out_size)
{
    const float* x  = (const float*)d_in[0];
    const float* z  = (const float*)d_in[1];
    const float* h0 = (const float*)d_in[2];
    const float* Wx = (const float*)d_in[3];
    const float* Wh = (const float*)d_in[4];
    const float* b  = (const float*)d_in[5];
    const float* gz = (const float*)d_in[6];
    const float* gh = (const float*)d_in[7];
    const float* bg = (const float*)d_in[8];

    float* out  = (float*)d_out;                       // [T,B,D]
    float* hout = out + (size_t)T_STEPS * BD;          // [T+1,B,D]

    init_kernel<<<64, 256>>>();                        // zero flags

    dim3 gGemm(1024 / 64, (T_STEPS * B_SZ) / 64);      // (16, 512)
    xp_gemm_kernel<<<gGemm, 256>>>(x, Wx, b);

    // actual need ~41KB; pad to force 1 CTA/SM (all 128 CTAs resident,
    // required for the dataflow flags to make progress).
    const int smem_bytes = 118784;
    cudaFuncSetAttribute(recur_kernel,
                         cudaFuncAttributeMaxDynamicSharedMemorySize, smem_bytes);
    recur_kernel<<<NCTA, NTHR, smem_bytes>>>(z, h0, Wh, gz, gh, bg, out, hout);
}

// round 8
// speedup vs baseline: 2.2842x; 2.2842x over previous
#include <cuda_runtime.h>
#include <cstdint>

#define T_STEPS 2048
#define B_SZ    16
#define D_SZ    1024
#define BD      (B_SZ*D_SZ)          /* 16384 */
#define NCTA    128
#define NTHR    512
#define BG_N    4                    /* batch rows per CTA */
#define CG_N    32                   /* columns per CTA */
#define GROUPS  4                    /* independent sync domains */
#define GSIZE   32                   /* CTAs per domain */

// 128 MB scratch for the precomputed input projection (allowed: __device__ global)
__device__ float    g_xp[(size_t)T_STEPS * BD];
// one monotonic arrival counter per batch-group, padded to separate L2 lines
__device__ unsigned g_cnt[GROUPS * 32];

// ---------------- packed fp32x2 helpers (sm_100+ PTX) ----------------
__device__ __forceinline__ void ffma2(unsigned long long &d,
                                      unsigned long long a,
                                      unsigned long long b) {
    asm("fma.rn.f32x2 %0, %1, %2, %0;" : "+l"(d) : "l"(a), "l"(b));
}
__device__ __forceinline__ unsigned long long dup2(float a) {
    unsigned long long r;
    asm("mov.b64 %0, {%1, %1};" : "=l"(r) : "f"(a));
    return r;
}
__device__ __forceinline__ float2 unpack2(unsigned long long v) {
    float2 r;
    asm("mov.b64 {%0, %1}, %2;" : "=f"(r.x), "=f"(r.y) : "l"(v));
    return r;
}
__device__ __forceinline__ void cp16(uint32_t dst_smem, const void* src) {
    asm volatile("cp.async.cg.shared.global [%0], [%1], 16;"
                 :: "r"(dst_smem), "l"(src) : "memory");
}
#define CP_COMMIT() asm volatile("cp.async.commit_group;" ::: "memory")
#define CP_WAIT0()  asm volatile("cp.async.wait_group 0;" ::: "memory")

// ---------------- sync primitives (R5-proven pattern) ----------------
__device__ __forceinline__ unsigned ld_acq(const unsigned* p) {
    unsigned v;
    asm volatile("ld.acquire.gpu.global.u32 %0, [%1];" : "=r"(v) : "l"(p) : "memory");
    return v;
}
__device__ __forceinline__ void red_rel(unsigned* p) {
    asm volatile("red.add.release.gpu.global.u32 [%0], 1;" :: "l"(p) : "memory");
}

__global__ void init_kernel() {
    if (threadIdx.x < GROUPS * 32) g_cnt[threadIdx.x] = 0u;
}

// ---------------------------------------------------------------------
// Kernel 1: xp[m,e] = sum_d x[m,d]*Wx[e,d] + b[e]   (unchanged)
// ---------------------------------------------------------------------
__global__ __launch_bounds__(256) void xp_gemm_kernel(
    const float* __restrict__ X,
    const float* __restrict__ Wx,
    const float* __restrict__ bias)
{
    __shared__ __align__(16) float As[16][68];
    __shared__ __align__(16) float Bs[16][68];

    const int tid   = threadIdx.x;
    const int mBase = blockIdx.y * 64;
    const int nBase = blockIdx.x * 64;

    const int lrow = tid >> 2;
    const int lk4  = (tid & 3) << 2;
    const int ty = tid >> 4;
    const int tx = tid & 15;

    unsigned long long acc[4][2];
#pragma unroll
    for (int i = 0; i < 4; i++) { acc[i][0] = 0ull; acc[i][1] = 0ull; }

    for (int k0 = 0; k0 < 1024; k0 += 16) {
        float4 av = *reinterpret_cast<const float4*>(
            &X[(size_t)(mBase + lrow) * 1024 + k0 + lk4]);
        float4 bv = *reinterpret_cast<const float4*>(
            &Wx[(size_t)(nBase + lrow) * 1024 + k0 + lk4]);
        As[lk4 + 0][lrow] = av.x; As[lk4 + 1][lrow] = av.y;
        As[lk4 + 2][lrow] = av.z; As[lk4 + 3][lrow] = av.w;
        Bs[lk4 + 0][lrow] = bv.x; Bs[lk4 + 1][lrow] = bv.y;
        Bs[lk4 + 2][lrow] = bv.z; Bs[lk4 + 3][lrow] = bv.w;
        __syncthreads();

#pragma unroll
        for (int k = 0; k < 16; k++) {
            float4 a = *reinterpret_cast<const float4*>(&As[k][ty << 2]);
            ulonglong2 bp = *reinterpret_cast<const ulonglong2*>(&Bs[k][tx << 2]);
            unsigned long long a0 = dup2(a.x), a1 = dup2(a.y);
            unsigned long long a2 = dup2(a.z), a3 = dup2(a.w);
            ffma2(acc[0][0], a0, bp.x); ffma2(acc[0][1], a0, bp.y);
            ffma2(acc[1][0], a1, bp.x); ffma2(acc[1][1], a1, bp.y);
            ffma2(acc[2][0], a2, bp.x); ffma2(acc[2][1], a2, bp.y);
            ffma2(acc[3][0], a3, bp.x); ffma2(acc[3][1], a3, bp.y);
        }
        __syncthreads();
    }

    const int col = nBase + (tx << 2);
    const float4 bv = *reinterpret_cast<const float4*>(&bias[col]);
#pragma unroll
    for (int m = 0; m < 4; m++) {
        const int row = mBase + (ty << 2) + m;
        float2 c01 = unpack2(acc[m][0]);
        float2 c23 = unpack2(acc[m][1]);
        float4 r;
        r.x = c01.x + bv.x; r.y = c01.y + bv.y;
        r.z = c23.x + bv.z; r.w = c23.y + bv.w;
        *reinterpret_cast<float4*>(&g_xp[(size_t)row * 1024 + col]) = r;
    }
}

// ---------------------------------------------------------------------
// Kernel 2: persistent recurrence; batch rows are INDEPENDENT chains.
// 128 CTAs x 512 threads = 4 independent groups (bg = cta&3, 4 b-rows
// each) x 32 col-slices (ng = cta>>2, 32 cols each). Zero cross-group
// coupling. Per step a CTA stages only 16KB of h (its 4 b-rows; chip
// 2MB/step), computes 4x32 outputs over full K, and syncs with just
// its 31 group peers via one monotonic counter (red.release arrive,
// tid0 ld.acquire poll). W_h (64 floats/thread) register-resident.
// Thread = (warp ks = k-sixteenth, lane n = column): h reads are pure
// intra-warp broadcast; reduce reads are consecutive-word conflict-free.
// ---------------------------------------------------------------------
__global__ __launch_bounds__(512, 1) void recur_kernel(
    const float* __restrict__ Z,
    const float* __restrict__ H0,
    const float* __restrict__ Wh,
    const float* __restrict__ Gz,
    const float* __restrict__ Gh,
    const float* __restrict__ Bg,
    float* __restrict__ Out,
    float* __restrict__ Hout)
{
    extern __shared__ __align__(16) float sm[];
    float* h_s = sm;                       // 4096 floats (16KB): [4][1024]
    float* red = sm + 4 * 1024;            // 2048 floats (8KB): [16][32][4]

    const int tid  = threadIdx.x;
    const int ks   = tid >> 5;             // k-sixteenth 0..15 (= warp)
    const int n    = tid & 31;             // column within CTA 0..31
    const int cta  = blockIdx.x;

    const int bg    = cta & 3;             // batch group (independent domain)
    const int ng    = cta >> 2;            // column slice 0..31
    const int bbase = bg * BG_N;
    const int gcol  = ng * CG_N + n;

    unsigned* cnt = &g_cnt[bg * 32];

    // ---- W_h slice (64 floats) -> registers, resident for all steps ----
    unsigned long long wx[16], wy[16];
    {
        const float* wp = Wh + (size_t)gcol * 1024 + ks * 64;
#pragma unroll
        for (int i = 0; i < 16; i++) {
            ulonglong2 v = *reinterpret_cast<const ulonglong2*>(wp + i * 4);
            wx[i] = v.x; wy[i] = v.y;
        }
    }

    // ---- epilogue role (threads 0..127): one output (b,col) each ----
    const int eb  = tid & 3;               // local b
    const int en  = tid >> 2;              // local col (0..31)
    const int egb = bbase + eb;
    const int egc = ng * CG_N + en;
    float gz_r = 0.f, gh_r = 0.f, bg_r = 0.f;
    if (tid < 128) {
        gz_r = Gz[egc]; gh_r = Gh[egc]; bg_r = Bg[egc];
        // h[0] = h0 (required output row 0; also the t=0 staging source)
        __stcg(&Hout[(size_t)egb * 1024 + egc], H0[(size_t)egb * 1024 + egc]);
    }
    __syncthreads();
    if (tid == 0) red_rel(cnt);            // publish h[0] slice

    const uint32_t h_sh = (uint32_t)__cvta_generic_to_shared(h_s);

    for (int t = 0; t < T_STEPS; ++t) {
        // ---- prefetch epilogue operands (independent of h) ----
        float xpv = 0.f, zv = 0.f;
        size_t eidx = 0;
        if (tid < 128) {
            eidx = (size_t)t * BD + (size_t)egb * 1024 + egc;
            xpv = __ldcg(&g_xp[eidx]);
            zv  = __ldcg(&Z[eidx]);
        }

        // ---- group barrier: wait for all 32 peers to publish h[t] ----
        if (tid == 0) {
            const unsigned target = (unsigned)GSIZE * (unsigned)(t + 1);
            while (ld_acq(cnt) < target) { }
        }
        __syncthreads();

        // ---- stage h[t] rows bbase..bbase+3 (16KB, fully coalesced) ----
        const float* hsrc = Hout + (size_t)t * BD + (size_t)bbase * 1024;
        cp16(h_sh + (uint32_t)tid * 16u,           hsrc + tid * 4);
        cp16(h_sh + (uint32_t)(tid + 512) * 16u,   hsrc + (tid + 512) * 4);
        CP_COMMIT();
        CP_WAIT0();
        __syncthreads();

        // ---- dot products: 256 MACs/thread (64k x 4b), h broadcast ----
        unsigned long long accA[4] = {0ull, 0ull, 0ull, 0ull};
        unsigned long long accB[4] = {0ull, 0ull, 0ull, 0ull};
        const float* hc = h_s + ks * 64;
#pragma unroll
        for (int i = 0; i < 16; i++) {
#pragma unroll
            for (int b = 0; b < 4; b++) {
                ulonglong2 hv = *reinterpret_cast<const ulonglong2*>(
                    hc + b * 1024 + i * 4);
                ffma2(accA[b], hv.x, wx[i]);
                ffma2(accB[b], hv.y, wy[i]);
            }
        }

        // ---- write 4 partials (one per b) to reduce buffer ----
        float s4[4];
#pragma unroll
        for (int b = 0; b < 4; b++) {
            float2 a = unpack2(accA[b]);
            float2 c = unpack2(accB[b]);
            s4[b] = (a.x + a.y) + (c.x + c.y);
        }
        *reinterpret_cast<float4*>(red + (ks * 32 + n) * 4) =
            make_float4(s4[0], s4[1], s4[2], s4[3]);
        __syncthreads();

        // ---- final reduce (16 k-partials, consecutive-word reads) ----
        float hn = 0.f, pre = 0.f;
        if (tid < 128) {
            float dot = 0.f;
#pragma unroll
            for (int k = 0; k < 16; k++)
                dot += red[k * 128 + tid];
            hn  = tanhf(xpv + dot);
            __stcg(&Hout[(size_t)(t + 1) * BD + (size_t)egb * 1024 + egc], hn);
            pre = zv * gz_r + hn * gh_r + bg_r;
        }
        __syncthreads();   // all Hout stores issued before arrival

        // ---- arrive (release); Out store off the critical path ----
        if (tid == 0) red_rel(cnt);
        if (tid < 128) {
            const float sg = 1.0f / (1.0f + __expf(-pre));
            __stcg(&Out[eidx], hn * (pre * sg));
        }
    }
}

// ---------------------------------------------------------------------
extern "C" void kernel_launch(void* const* d_in, const int* in_sizes, int n_in,
                              void* d_out, int out_size)
{
    const float* x  = (const float*)d_in[0];
    const float* z  = (const float*)d_in[1];
    const float* h0 = (const float*)d_in[2];
    const float* Wx = (const float*)d_in[3];
    const float* Wh = (const float*)d_in[4];
    const float* b  = (const float*)d_in[5];
    const float* gz = (const float*)d_in[6];
    const float* gh = (const float*)d_in[7];
    const float* bg = (const float*)d_in[8];

    float* out  = (float*)d_out;                       // [T,B,D]
    float* hout = out + (size_t)T_STEPS * BD;          // [T+1,B,D]

    init_kernel<<<1, 128>>>();                         // zero 4 counters

    dim3 gGemm(1024 / 64, (T_STEPS * B_SZ) / 64);      // (16, 512)
    xp_gemm_kernel<<<gGemm, 256>>>(x, Wx, b);

    // actual need 24KB; pad to force 1 CTA/SM (all 128 CTAs resident,
    // required for the group counters to make progress).
    const int smem_bytes = 118784;
    cudaFuncSetAttribute(recur_kernel,
                         cudaFuncAttributeMaxDynamicSharedMemorySize, smem_bytes);
    recur_kernel<<<NCTA, NTHR, smem_bytes>>>(z, h0, Wh, gz, gh, bg, out, hout);
}